// round 1
// baseline (speedup 1.0000x reference)
#include <cuda_runtime.h>
#include <cfloat>
#include <climits>

// Problem constants (fixed by the dataset)
#define B_ 2
#define NP_ 16
#define BN 32          // B_*NP_
#define SQ 1024
#define SK 2048
#define HN 128
#define TK 16

// GEMM tiling
#define TILE 128
#define SP 132         // smem row stride (floats), multiple of 4 for vector alignment
#define SMEM_BYTES (2 * TILE * SP * 4)

// ---------------- scratch (device globals; no allocations allowed) ----------------
__device__ float g_scores[(size_t)BN * SQ * SK];   // [n][s][t]
__device__ float g_tv[(size_t)BN * SQ * TK];       // top-16 raw scores
__device__ int   g_ti[(size_t)BN * SQ * TK];       // top-16 key indices

// ---------------- packed f32x2 helpers (sm_100+) ----------------
__device__ __forceinline__ void fma2(unsigned long long& acc, unsigned long long a,
                                     unsigned long long b) {
    asm("fma.rn.f32x2 %0, %1, %2, %0;" : "+l"(acc) : "l"(a), "l"(b));
}
__device__ __forceinline__ unsigned long long dup2(float a) {
    unsigned long long r;
    asm("mov.b64 %0, {%1, %1};" : "=l"(r) : "f"(a));
    return r;
}

// =====================================================================
// Kernel 1: scores[n][s][t] = sum_h Q[s,n,h] * K[t,n,h]   (fp32 exact-ish)
// CTA: 128q x 128t tile for one n. 256 threads, 8x8 micro-tile via f32x2.
// =====================================================================
__global__ void __launch_bounds__(256) k_scores(const float* __restrict__ Q,
                                                const float* __restrict__ K) {
    extern __shared__ float sm[];
    float* Qs = sm;               // [128 rows(q)][SP] row-major over h
    float* Ks = sm + TILE * SP;   // [128 (h)][SP] transposed: [h][t]

    const int n  = blockIdx.z;
    const int q0 = blockIdx.y * TILE;
    const int t0 = blockIdx.x * TILE;
    const int tid  = threadIdx.x;
    const int lane = tid & 31;
    const int warp = tid >> 5;

    // ---- load phase: coalesced LDG.128; Q stored row-major, K transposed ----
    const int lr = lane >> 3;   // 0..3 (row within 4-row group)
    const int lc = lane & 7;    // 0..7 (float4 column group)
    for (int rr = warp * 4; rr < TILE; rr += 32) {
        const int r = rr + lr;
        #pragma unroll
        for (int cc = 0; cc < 32; cc += 8) {
            const int c4 = cc + lc;
            float4 qv = *(const float4*)(Q + ((size_t)(q0 + r) * BN + n) * HN + c4 * 4);
            *(float4*)(Qs + r * SP + c4 * 4) = qv;
            float4 kv = *(const float4*)(K + ((size_t)(t0 + r) * BN + n) * HN + c4 * 4);
            Ks[(c4 * 4 + 0) * SP + r] = kv.x;
            Ks[(c4 * 4 + 1) * SP + r] = kv.y;
            Ks[(c4 * 4 + 2) * SP + r] = kv.z;
            Ks[(c4 * 4 + 3) * SP + r] = kv.w;
        }
    }
    __syncthreads();

    // ---- compute phase ----
    const int tx = tid & 15;    // key dir: keys tx*8 .. tx*8+7
    const int ty = tid >> 4;    // query dir: queries ty*8 .. ty*8+7
    const float* qsbase = Qs + (ty * 8) * SP;
    const float* ksbase = Ks + tx * 8;

    unsigned long long acc[8][4] = {};

    #pragma unroll 2
    for (int h = 0; h < HN; h += 4) {
        float4 a4[8];
        #pragma unroll
        for (int i = 0; i < 8; i++)
            a4[i] = *(const float4*)(qsbase + i * SP + h);
        #pragma unroll
        for (int hh = 0; hh < 4; hh++) {
            const float* kr = ksbase + (h + hh) * SP;
            unsigned long long b0 = *(const unsigned long long*)(kr + 0);
            unsigned long long b1 = *(const unsigned long long*)(kr + 2);
            unsigned long long b2 = *(const unsigned long long*)(kr + 4);
            unsigned long long b3 = *(const unsigned long long*)(kr + 6);
            #pragma unroll
            for (int i = 0; i < 8; i++) {
                float a = (hh == 0) ? a4[i].x : (hh == 1) ? a4[i].y
                        : (hh == 2) ? a4[i].z : a4[i].w;
                unsigned long long a2 = dup2(a);
                fma2(acc[i][0], a2, b0);
                fma2(acc[i][1], a2, b1);
                fma2(acc[i][2], a2, b2);
                fma2(acc[i][3], a2, b3);
            }
        }
    }

    // ---- write-out ----
    #pragma unroll
    for (int i = 0; i < 8; i++) {
        float* out = g_scores + ((size_t)(n * SQ + q0 + ty * 8 + i)) * SK + t0 + tx * 8;
        #pragma unroll
        for (int jp = 0; jp < 4; jp++) {
            union { unsigned long long u; float2 f; } cvt;
            cvt.u = acc[i][jp];
            *(float2*)(out + 2 * jp) = cvt.f;
        }
    }
}

// =====================================================================
// Kernel 2: exact top-16 per query row (2048 keys) via histogram threshold
// One 128-thread CTA per query. Tie-break: equal value -> lower index
// (matches jax.lax.top_k set membership).
// =====================================================================
__device__ __forceinline__ int binOf(float v) {
    int b = (int)((v + 128.f) * 4.f);   // 1024 bins over [-128, 128)
    return min(1023, max(0, b));
}

__global__ void __launch_bounds__(128) k_topk() {
    __shared__ float sc[SK];
    __shared__ int   hist[1024];
    __shared__ int   csum[128];
    __shared__ float cv[SK];
    __shared__ int   ci[SK];
    __shared__ int   s_cnt, s_bin;
    __shared__ float rv[128];
    __shared__ int   ri[128];
    __shared__ int   rs[128];

    const int tid = threadIdx.x;
    const size_t q = blockIdx.x;                 // q = n*SQ + s
    const float* row = g_scores + q * SK;

    for (int i = tid; i < 1024; i += 128) hist[i] = 0;
    __syncthreads();

    for (int i = tid; i < SK; i += 128) {
        float v = row[i];
        sc[i] = v;
        atomicAdd(&hist[binOf(v)], 1);
    }
    __syncthreads();

    int c0 = 0;
    #pragma unroll
    for (int j = 0; j < 8; j++) c0 += hist[tid * 8 + j];
    csum[tid] = c0;
    __syncthreads();

    if (tid == 0) {
        int acc = 0, b = 127;
        for (; b >= 0; --b) { acc += csum[b]; if (acc >= TK) break; }
        s_bin = b * 8;     // candidates: bins >= s_bin (count >= 16)
        s_cnt = 0;
    }
    __syncthreads();

    const int bmin = s_bin;
    for (int i = tid; i < SK; i += 128) {
        float v = sc[i];
        if (binOf(v) >= bmin) {
            int p = atomicAdd(&s_cnt, 1);
            cv[p] = v;
            ci[p] = i;
        }
    }
    __syncthreads();
    const int C = s_cnt;

    for (int t = 0; t < TK; t++) {
        float bv = -FLT_MAX; int bi = INT_MAX; int bslot = -1;
        for (int i = tid; i < C; i += 128) {
            float v = cv[i]; int ix = ci[i];
            if (v > bv || (v == bv && ix < bi)) { bv = v; bi = ix; bslot = i; }
        }
        rv[tid] = bv; ri[tid] = bi; rs[tid] = bslot;
        __syncthreads();
        if (tid < 32) {
            #pragma unroll
            for (int o = 32; o < 128; o += 32) {
                float v = rv[tid + o]; int ix = ri[tid + o];
                if (v > bv || (v == bv && ix < bi)) { bv = v; bi = ix; bslot = rs[tid + o]; }
            }
            #pragma unroll
            for (int o = 16; o > 0; o >>= 1) {
                float v  = __shfl_down_sync(0xffffffff, bv, o);
                int   ix = __shfl_down_sync(0xffffffff, bi, o);
                int   sl = __shfl_down_sync(0xffffffff, bslot, o);
                if (v > bv || (v == bv && ix < bi)) { bv = v; bi = ix; bslot = sl; }
            }
            if (tid == 0) {
                g_tv[q * TK + t] = bv;
                g_ti[q * TK + t] = bi;
                cv[bslot] = -FLT_MAX;
                ci[bslot] = INT_MAX;
            }
        }
        __syncthreads();
    }
}

// =====================================================================
// Kernel 3: softmax over 16 + weighted V gather. One warp per query.
// =====================================================================
__global__ void __launch_bounds__(256) k_attend(const float* __restrict__ V,
                                                float* __restrict__ O) {
    __shared__ float swt[8][TK];
    __shared__ int   sid[8][TK];
    const int wi = threadIdx.x >> 5;
    const int lane = threadIdx.x & 31;
    const size_t q = (size_t)blockIdx.x * 8 + wi;
    const int n = (int)(q >> 10);   // q = n*SQ + s

    const float inv_norm = 0.08838834764831845f;  // 1/sqrt(128)
    float l = -FLT_MAX;
    int myi = 0;
    if (lane < TK) {
        l = g_tv[q * TK + lane] * inv_norm;
        myi = g_ti[q * TK + lane];
    }
    float m = l;
    #pragma unroll
    for (int o = 16; o > 0; o >>= 1) m = fmaxf(m, __shfl_xor_sync(0xffffffff, m, o));
    float p = (lane < TK) ? expf(l - m) : 0.f;
    float Z = p;
    #pragma unroll
    for (int o = 16; o > 0; o >>= 1) Z += __shfl_xor_sync(0xffffffff, Z, o);
    if (lane < TK) {
        swt[wi][lane] = p / Z;
        sid[wi][lane] = myi;
    }
    __syncwarp();

    float4 acc = make_float4(0.f, 0.f, 0.f, 0.f);
    const float4* Vb = (const float4*)V;
    #pragma unroll
    for (int t = 0; t < TK; t++) {
        const int kt = sid[wi][t];
        const float wg = swt[wi][t];
        float4 vv = Vb[((size_t)kt * BN + n) * (HN / 4) + lane];
        acc.x += wg * vv.x;
        acc.y += wg * vv.y;
        acc.z += wg * vv.z;
        acc.w += wg * vv.w;
    }
    ((float4*)O)[q * (HN / 4) + lane] = acc;
}

// =====================================================================
extern "C" void kernel_launch(void* const* d_in, const int* in_sizes, int n_in,
                              void* d_out, int out_size) {
    const float* Q = (const float*)d_in[0];
    const float* K = (const float*)d_in[1];
    const float* V = (const float*)d_in[2];
    // d_in[3] = knn_key_count, fixed at 16 (TK)
    float* O = (float*)d_out;

    cudaFuncSetAttribute(k_scores, cudaFuncAttributeMaxDynamicSharedMemorySize, SMEM_BYTES);

    dim3 g1(SK / TILE, SQ / TILE, BN);   // 16 x 8 x 32
    k_scores<<<g1, 256, SMEM_BYTES>>>(Q, K);
    k_topk<<<BN * SQ, 128>>>();
    k_attend<<<BN * SQ / 8, 256>>>(V, O);
}

// round 2
// speedup vs baseline: 1.9067x; 1.9067x over previous
#include <cuda_runtime.h>
#include <cfloat>
#include <climits>

// Problem constants (fixed by the dataset)
#define B_ 2
#define NP_ 16
#define BN 32          // B_*NP_
#define SQ 1024
#define SK 2048
#define HN 128
#define TK 16

// GEMM tiling
#define TILE 128
#define HC 32          // h-chunk
#define QSP 36         // Q smem row stride (floats)
#define KSP 132        // K smem row stride (floats)

// ---------------- scratch (device globals; no allocations allowed) ----------------
__device__ float g_scores[(size_t)BN * SQ * SK];   // [n][s][t]

// ---------------- packed f32x2 helpers (sm_100+) ----------------
__device__ __forceinline__ void fma2(unsigned long long& acc, unsigned long long a,
                                     unsigned long long b) {
    asm("fma.rn.f32x2 %0, %1, %2, %0;" : "+l"(acc) : "l"(a), "l"(b));
}
__device__ __forceinline__ unsigned long long dup2(float a) {
    unsigned long long r;
    asm("mov.b64 %0, {%1, %1};" : "=l"(r) : "f"(a));
    return r;
}

// =====================================================================
// Kernel 1: scores[n][s][t] = sum_h Q[s,n,h] * K[t,n,h]   (fp32)
// CTA: 128q x 128t tile for one n, h chunked by 32 (35KB smem -> 2 CTA/SM).
// Thread (ty,tx): queries ty*8..+7, key pairs {2tx+32j, +1} j=0..3
// (conflict-free LDS.64 on K).
// =====================================================================
__global__ void __launch_bounds__(256, 2) k_scores(const float* __restrict__ Q,
                                                   const float* __restrict__ K) {
    __shared__ float Qs[TILE * QSP];   // [q][h-chunk]
    __shared__ float Ks[HC * KSP];     // [h-chunk][t] transposed

    const int n  = blockIdx.z;
    const int q0 = blockIdx.y * TILE;
    const int t0 = blockIdx.x * TILE;
    const int tid = threadIdx.x;
    const int tx = tid & 15;
    const int ty = tid >> 4;

    unsigned long long acc[8][4] = {};

    const float* qsbase = Qs + (ty * 8) * QSP;
    const float* ksbase = Ks + 2 * tx;

    for (int hb = 0; hb < HN; hb += HC) {
        // ---- load chunk: 128 rows x 32 h each for Q and K ----
        #pragma unroll
        for (int kk = 0; kk < 4; kk++) {
            const int f = tid + kk * 256;       // 0..1023
            const int r = f >> 3;                // row 0..127
            const int c4 = f & 7;                // float4 col 0..7
            float4 qv = *(const float4*)(Q + ((size_t)(q0 + r) * BN + n) * HN + hb + c4 * 4);
            *(float4*)(Qs + r * QSP + c4 * 4) = qv;
            float4 kv = *(const float4*)(K + ((size_t)(t0 + r) * BN + n) * HN + hb + c4 * 4);
            Ks[(c4 * 4 + 0) * KSP + r] = kv.x;
            Ks[(c4 * 4 + 1) * KSP + r] = kv.y;
            Ks[(c4 * 4 + 2) * KSP + r] = kv.z;
            Ks[(c4 * 4 + 3) * KSP + r] = kv.w;
        }
        __syncthreads();

        // ---- compute chunk ----
        #pragma unroll 2
        for (int h = 0; h < HC; h += 4) {
            float4 a4[8];
            #pragma unroll
            for (int i = 0; i < 8; i++)
                a4[i] = *(const float4*)(qsbase + i * QSP + h);
            #pragma unroll
            for (int hh = 0; hh < 4; hh++) {
                const float* kr = ksbase + (h + hh) * KSP;
                unsigned long long b0 = *(const unsigned long long*)(kr + 0);
                unsigned long long b1 = *(const unsigned long long*)(kr + 32);
                unsigned long long b2 = *(const unsigned long long*)(kr + 64);
                unsigned long long b3 = *(const unsigned long long*)(kr + 96);
                #pragma unroll
                for (int i = 0; i < 8; i++) {
                    float a = (hh == 0) ? a4[i].x : (hh == 1) ? a4[i].y
                            : (hh == 2) ? a4[i].z : a4[i].w;
                    unsigned long long a2 = dup2(a);
                    fma2(acc[i][0], a2, b0);
                    fma2(acc[i][1], a2, b1);
                    fma2(acc[i][2], a2, b2);
                    fma2(acc[i][3], a2, b3);
                }
            }
        }
        __syncthreads();
    }

    // ---- write-out: key columns t0 + 2*tx + 32*jp (+0,+1) ----
    #pragma unroll
    for (int i = 0; i < 8; i++) {
        float* out = g_scores + ((size_t)(n * SQ + q0 + ty * 8 + i)) * SK + t0 + 2 * tx;
        #pragma unroll
        for (int jp = 0; jp < 4; jp++) {
            union { unsigned long long u; float2 f; } cvt;
            cvt.u = acc[i][jp];
            *(float2*)(out + 32 * jp) = cvt.f;
        }
    }
}

// =====================================================================
// Kernel 2 (fused top-16 + softmax + V gather): one warp per query.
// Scores held in 64 regs/lane; stats-seeded threshold + bisection prune
// -> exact 16 argmax rounds (tie: lower index) -> softmax -> V gather.
// =====================================================================
__global__ void __launch_bounds__(256) k_select(const float* __restrict__ V,
                                                float* __restrict__ O) {
    __shared__ float cv[8][128];
    __shared__ int   cix[8][128];
    __shared__ int   ccnt[8];

    const int wi   = threadIdx.x >> 5;
    const int lane = threadIdx.x & 31;
    const size_t q = (size_t)blockIdx.x * 8 + wi;
    const int n = (int)(q >> 10);              // q = n*SQ + s

    const float4* r4 = (const float4*)(g_scores + q * SK);

    // load 64 scores per lane (coalesced)
    float v[64];
    #pragma unroll
    for (int j = 0; j < 16; j++) {
        float4 t = r4[j * 32 + lane];
        v[4 * j + 0] = t.x; v[4 * j + 1] = t.y;
        v[4 * j + 2] = t.z; v[4 * j + 3] = t.w;
    }

    // warp stats
    float s1 = 0.f, s2 = 0.f, mx = -FLT_MAX, mn = FLT_MAX;
    #pragma unroll
    for (int j = 0; j < 64; j++) {
        float x = v[j];
        s1 += x; s2 = fmaf(x, x, s2);
        mx = fmaxf(mx, x); mn = fminf(mn, x);
    }
    #pragma unroll
    for (int o = 16; o; o >>= 1) {
        s1 += __shfl_xor_sync(0xffffffffu, s1, o);
        s2 += __shfl_xor_sync(0xffffffffu, s2, o);
        mx = fmaxf(mx, __shfl_xor_sync(0xffffffffu, mx, o));
        mn = fminf(mn, __shfl_xor_sync(0xffffffffu, mn, o));
    }
    const float mu  = s1 * (1.f / 2048.f);
    const float sig = sqrtf(fmaxf(s2 * (1.f / 2048.f) - mu * mu, 0.f));

    // threshold search: want 16 <= cnt(>=T) <= 128
    float Tlo = mn, Thi = mx;
    float T = mu + 2.2f * sig;
    if (!(T > mn && T < mx)) T = 0.5f * (mn + mx);
    int cnt = 0;
    bool ok = false;
    for (int it = 0; it < 40; it++) {
        cnt = 0;
        #pragma unroll
        for (int j = 0; j < 64; j++) cnt += (v[j] >= T) ? 1 : 0;
        #pragma unroll
        for (int o = 16; o; o >>= 1) cnt += __shfl_xor_sync(0xffffffffu, cnt, o);
        if (cnt >= TK && cnt <= 128) { ok = true; break; }
        if (cnt < TK) Thi = T; else Tlo = T;
        float Tn = 0.5f * (Tlo + Thi);
        if (Tn == Tlo || Tn == Thi) break;     // bracket exhausted
        T = Tn;
    }

    float selv = -FLT_MAX;   // lane t (t<16) holds the t-th selected value
    int   seli = INT_MAX;

    if (lane == 0) ccnt[wi] = 0;
    __syncwarp();

    if (ok) {
        // ---- compact candidates to smem ----
        #pragma unroll
        for (int j = 0; j < 64; j++) {
            if (v[j] >= T) {
                int p = atomicAdd(&ccnt[wi], 1);
                cv[wi][p]  = v[j];
                cix[wi][p] = (((j >> 2) * 32 + lane) << 2) + (j & 3);
            }
        }
        __syncwarp();
        const int C = ccnt[wi];
        for (int p = C + lane; p < 128; p += 32) {
            cv[wi][p] = -FLT_MAX; cix[wi][p] = INT_MAX;
        }
        __syncwarp();

        // ---- 16 exact argmax rounds over <=128 candidates ----
        for (int t = 0; t < TK; t++) {
            float bv = -FLT_MAX; int bi = INT_MAX; int bs = 0;
            #pragma unroll
            for (int k = 0; k < 4; k++) {
                int s = lane + k * 32;
                float xv = cv[wi][s]; int xi = cix[wi][s];
                if (xv > bv || (xv == bv && xi < bi)) { bv = xv; bi = xi; bs = s; }
            }
            #pragma unroll
            for (int o = 16; o; o >>= 1) {
                float xv = __shfl_xor_sync(0xffffffffu, bv, o);
                int   xi = __shfl_xor_sync(0xffffffffu, bi, o);
                int   xs = __shfl_xor_sync(0xffffffffu, bs, o);
                if (xv > bv || (xv == bv && xi < bi)) { bv = xv; bi = xi; bs = xs; }
            }
            if (lane == t) { selv = bv; seli = bi; }
            if (lane == 0) { cv[wi][bs] = -FLT_MAX; cix[wi][bs] = INT_MAX; }
            __syncwarp();
        }
    } else {
        // ---- fallback: exact extraction from registers (pathological ties) ----
        unsigned long long dead = 0ull;
        for (int t = 0; t < TK; t++) {
            float bv = -FLT_MAX; int bj = -1;
            #pragma unroll
            for (int j = 0; j < 64; j++) {
                bool alive = !((dead >> j) & 1ull);
                if (alive && v[j] > bv) { bv = v[j]; bj = j; }
            }
            int bidx = (bj < 0) ? INT_MAX
                     : ((((bj >> 2) * 32 + lane) << 2) + (bj & 3));
            float rv = bv; int ri = bidx; int rl = lane; int rj = bj;
            #pragma unroll
            for (int o = 16; o; o >>= 1) {
                float xv = __shfl_xor_sync(0xffffffffu, rv, o);
                int   xi = __shfl_xor_sync(0xffffffffu, ri, o);
                int   xl = __shfl_xor_sync(0xffffffffu, rl, o);
                int   xj = __shfl_xor_sync(0xffffffffu, rj, o);
                if (xv > rv || (xv == rv && xi < ri)) { rv = xv; ri = xi; rl = xl; rj = xj; }
            }
            if (lane == t) { selv = rv; seli = ri; }
            if (lane == rl) dead |= (1ull << rj);
        }
    }

    // ---- softmax over the 16 (fp32) ----
    const float inv_norm = 0.08838834764831845f;    // 1/sqrt(128)
    float l = (lane < TK) ? selv * inv_norm : -FLT_MAX;
    float m = l;
    #pragma unroll
    for (int o = 16; o; o >>= 1) m = fmaxf(m, __shfl_xor_sync(0xffffffffu, m, o));
    float p = (lane < TK) ? expf(l - m) : 0.f;
    float Z = p;
    #pragma unroll
    for (int o = 16; o; o >>= 1) Z += __shfl_xor_sync(0xffffffffu, Z, o);
    const float wgt = p / Z;

    // ---- V gather: 16 rows x 128 floats, warp-wide float4 ----
    float4 acc = make_float4(0.f, 0.f, 0.f, 0.f);
    const float4* V4 = (const float4*)V;
    #pragma unroll
    for (int t = 0; t < TK; t++) {
        float wt = __shfl_sync(0xffffffffu, wgt, t);
        int   kt = __shfl_sync(0xffffffffu, seli, t);
        float4 vv = V4[((size_t)kt * BN + n) * (HN / 4) + lane];
        acc.x = fmaf(wt, vv.x, acc.x);
        acc.y = fmaf(wt, vv.y, acc.y);
        acc.z = fmaf(wt, vv.z, acc.z);
        acc.w = fmaf(wt, vv.w, acc.w);
    }
    ((float4*)O)[q * (HN / 4) + lane] = acc;
}

// =====================================================================
extern "C" void kernel_launch(void* const* d_in, const int* in_sizes, int n_in,
                              void* d_out, int out_size) {
    const float* Q = (const float*)d_in[0];
    const float* K = (const float*)d_in[1];
    const float* V = (const float*)d_in[2];
    // d_in[3] = knn_key_count, fixed at 16 (TK)
    float* O = (float*)d_out;

    dim3 g1(SK / TILE, SQ / TILE, BN);   // 16 x 8 x 32
    k_scores<<<g1, 256>>>(Q, K);
    k_select<<<BN * SQ / 8, 256>>>(V, O);
}